// round 5
// baseline (speedup 1.0000x reference)
#include <cuda_runtime.h>
#include <cuda_bf16.h>
#include <cstdint>
#include <math.h>

#define BB 8
#define TT 256
#define VV 32
#define DD 256
#define NELEM (BB * TT * VV * DD)

// ---------------- scratch (no cudaMalloc allowed) ----------------
__device__ float g_ap[BB * TT];   // [i,k]
__device__ float g_neg[BB * TT];  // [i,q]
__device__ __nv_bfloat16 g_fbf[NELEM];   // feature     as [B][V][T][D] bf16
__device__ __nv_bfloat16 g_fabf[NELEM];  // feature_aug as [B][V][T][D] bf16

__device__ __forceinline__ uint32_t smem_to_u32(const void* p) {
    uint32_t a;
    asm("{ .reg .u64 t; cvta.to.shared.u64 t, %1; cvt.u32.u64 %0, t; }" : "=r"(a) : "l"(p));
    return a;
}

#define CP_ASYNC16(dst, src) \
    asm volatile("cp.async.cg.shared.global [%0], [%1], 16;" :: "r"(dst), "l"(src) : "memory")
#define CP_COMMIT() asm volatile("cp.async.commit_group;" ::: "memory")
#define CP_WAIT(n)  asm volatile("cp.async.wait_group %0;" :: "n"(n) : "memory")

#define LDMATRIX_X4(r0, r1, r2, r3, addr) \
    asm volatile("ldmatrix.sync.aligned.m8n8.x4.shared.b16 {%0,%1,%2,%3}, [%4];" \
                 : "=r"(r0), "=r"(r1), "=r"(r2), "=r"(r3) : "r"(addr))

#define MMA16816(c, a0, a1, a2, a3, b0, b1) \
    asm volatile("mma.sync.aligned.m16n8k16.row.col.f32.bf16.bf16.f32 " \
                 "{%0,%1,%2,%3}, {%4,%5,%6,%7}, {%8,%9}, {%0,%1,%2,%3};" \
                 : "+f"((c)[0]), "+f"((c)[1]), "+f"((c)[2]), "+f"((c)[3]) \
                 : "r"(a0), "r"(a1), "r"(a2), "r"(a3), "r"(b0), "r"(b1))

// SMEM: 3 stages; stage s: A at s*49152 (128 rows x 128B), B at +16384 (256 rows x 128B)
#define STAGE_STRIDE 49152
#define A_OFF(s) ((s) * STAGE_STRIDE)
#define B_OFF(s) ((s) * STAGE_STRIDE + 16384)
#define SMEM_DYN (3 * STAGE_STRIDE)  // 147456

// ---------------- kernels ----------------
__global__ void init_kernel() {
    int t = blockIdx.x * blockDim.x + threadIdx.x;
    if (t < BB * TT) { g_ap[t] = 0.0f; g_neg[t] = 0.0f; }
}

// fp32 [B][T][V][D] -> bf16 [B][V][T][D]
__global__ __launch_bounds__(256) void convert_kernel(const float* __restrict__ f,
                                                      const float* __restrict__ fa) {
    const float* src = (blockIdx.y == 0) ? f : fa;
    __nv_bfloat16* dst = (blockIdx.y == 0) ? g_fbf : g_fabf;
    long long e = ((long long)blockIdx.x * 256 + threadIdx.x) * 4;
    if (e >= NELEM) return;
    int d = (int)(e & 255);
    long long r = e >> 8;
    int v = (int)(r & 31);
    r >>= 5;
    int t = (int)(r & 255);
    int b = (int)(r >> 8);
    float4 x = *(const float4*)(src + e);
    __nv_bfloat162 lo = __floats2bfloat162_rn(x.x, x.y);
    __nv_bfloat162 hi = __floats2bfloat162_rn(x.z, x.w);
    long long o = (((long long)(b * VV + v) * TT + t) * DD + d);
    *(__nv_bfloat162*)(dst + o)     = lo;
    *(__nv_bfloat162*)(dst + o + 2) = hi;
}

// One CTA: 128(M) x 256(N) x 256(K) tile of one (i,j,v) pair + fused exp/row-sum.
// blockIdx.y = pair p: i=p>>8, j=(p>>5)&7, v=p&31.  blockIdx.x = mtile.
// off-diag: A = f[i,v] rows q (M), B = fa[j,v] all k (N) -> row-sum -> g_neg[i,q]
// diag    : A = fa[i,v] rows k (M), B = f[i,v] all q (N) -> row-sum -> g_ap[i,k]
__global__ __launch_bounds__(256, 1) void pair_mma_kernel() {
    extern __shared__ char smem[];
    __shared__ float red[128];
    const uint32_t smem_base = smem_to_u32(smem);

    const int tid  = threadIdx.x;
    const int lane = tid & 31;
    const int wid  = tid >> 5;
    const int warp_m = wid & 1;   // 2 warp rows (64 M each)
    const int warp_n = wid >> 1;  // 4 warp cols (64 N each)

    const int p = blockIdx.y;
    const int v = p & 31;
    const int j = (p >> 5) & 7;
    const int i = p >> 8;
    const int mtile = blockIdx.x;
    const bool diag = (i == j);

    const __nv_bfloat16* Apg = (diag ? g_fabf : g_fbf)
        + ((long long)(i * VV + v) * TT + mtile * 128) * DD;
    const __nv_bfloat16* Bpg = (diag ? g_fbf : g_fabf)
        + ((long long)((diag ? i : j) * VV + v) * TT) * DD;

    if (tid < 128) red[tid] = 0.0f;

    float c[4][8][4];
#pragma unroll
    for (int mi = 0; mi < 4; mi++)
#pragma unroll
        for (int ni = 0; ni < 8; ni++)
#pragma unroll
            for (int e = 0; e < 4; e++) c[mi][ni][e] = 0.0f;

    const int l15 = lane & 15;
    const int l7  = lane & 7;
    const int lhi = lane >> 4;
    const uint32_t a_lane_base = smem_base + (warp_m * 64 + l15) * 128;
    const uint32_t b_lane_base = smem_base + (warp_n * 64 + l15) * 128;

    // stage fill: 3072 x 16B per chunk (A: 1024, B: 2048), 12 per thread
#define ISSUE_CHUNK(chunk)                                                               \
    do {                                                                                 \
        const int _s = (chunk) % 3;                                                      \
        const int _d0 = (chunk) * 64;                                                    \
        _Pragma("unroll")                                                                \
        for (int t = 0; t < 12; t++) {                                                   \
            int idx = tid + t * 256;                                                     \
            if (idx < 1024) {                                                            \
                int row = idx >> 3, seg = idx & 7;                                       \
                const __nv_bfloat16* src = Apg + row * DD + _d0 + seg * 8;               \
                uint32_t dst = smem_base + A_OFF(_s)                                     \
                               + row * 128 + (((seg ^ (row & 7))) << 4);                 \
                CP_ASYNC16(dst, src);                                                    \
            } else {                                                                     \
                int li = idx - 1024;                                                     \
                int row = li >> 3, seg = li & 7;                                         \
                const __nv_bfloat16* src = Bpg + row * DD + _d0 + seg * 8;               \
                uint32_t dst = smem_base + B_OFF(_s)                                     \
                               + row * 128 + (((seg ^ (row & 7))) << 4);                 \
                CP_ASYNC16(dst, src);                                                    \
            }                                                                            \
        }                                                                                \
        CP_COMMIT();                                                                     \
    } while (0)

    ISSUE_CHUNK(0);
    ISSUE_CHUNK(1);

#pragma unroll
    for (int ch = 0; ch < 4; ch++) {
        if (ch < 3) { CP_WAIT(1); } else { CP_WAIT(0); }
        __syncthreads();
        if (ch < 2) ISSUE_CHUNK(ch + 2);

        const int s = ch % 3;
        const uint32_t abase = a_lane_base + A_OFF(s);
        const uint32_t bbase = b_lane_base + B_OFF(s);
#pragma unroll
        for (int kk = 0; kk < 4; kk++) {
            const uint32_t swz = ((uint32_t)((kk * 2 + lhi) ^ l7)) << 4;
            uint32_t a[4][4];
#pragma unroll
            for (int mi = 0; mi < 4; mi++) {
                LDMATRIX_X4(a[mi][0], a[mi][1], a[mi][2], a[mi][3],
                            abase + mi * 16 * 128 + swz);
            }
#pragma unroll
            for (int nb = 0; nb < 4; nb++) {
                uint32_t r0, r1, r2, r3;
                LDMATRIX_X4(r0, r1, r2, r3, bbase + nb * 16 * 128 + swz);
#pragma unroll
                for (int mi = 0; mi < 4; mi++) {
                    MMA16816(c[mi][nb * 2 + 0], a[mi][0], a[mi][1], a[mi][2], a[mi][3], r0, r2);
                    MMA16816(c[mi][nb * 2 + 1], a[mi][0], a[mi][1], a[mi][2], a[mi][3], r1, r3);
                }
            }
        }
    }

    // epilogue: exp + row sums (rows = M dim)
#pragma unroll
    for (int mi = 0; mi < 4; mi++) {
        float s0 = 0.0f, s1 = 0.0f;
#pragma unroll
        for (int ni = 0; ni < 8; ni++) {
            s0 += __expf(c[mi][ni][0]) + __expf(c[mi][ni][1]);
            s1 += __expf(c[mi][ni][2]) + __expf(c[mi][ni][3]);
        }
        s0 += __shfl_xor_sync(0xFFFFFFFF, s0, 1);
        s0 += __shfl_xor_sync(0xFFFFFFFF, s0, 2);
        s1 += __shfl_xor_sync(0xFFFFFFFF, s1, 1);
        s1 += __shfl_xor_sync(0xFFFFFFFF, s1, 2);
        if ((lane & 3) == 0) {
            int r0 = warp_m * 64 + mi * 16 + (lane >> 2);
            atomicAdd(&red[r0], s0);
            atomicAdd(&red[r0 + 8], s1);
        }
    }
    __syncthreads();

    if (tid < 128) {
        int grow = mtile * 128 + tid;
        atomicAdd(diag ? &g_ap[i * TT + grow] : &g_neg[i * TT + grow], red[tid]);
    }
}

__global__ __launch_bounds__(1024) void finalize_kernel(float* __restrict__ out) {
    __shared__ float sred[1024];
    const int tid = threadIdx.x;
    float s = (logf(g_neg[tid]) - logf(g_ap[tid]))
            + (logf(g_neg[tid + 1024]) - logf(g_ap[tid + 1024]));
    sred[tid] = s;
    __syncthreads();
    for (int o = 512; o > 0; o >>= 1) {
        if (tid < o) sred[tid] += sred[tid + o];
        __syncthreads();
    }
    if (tid == 0) out[0] = sred[0] / (float)TT;
}

extern "C" void kernel_launch(void* const* d_in, const int* in_sizes, int n_in,
                              void* d_out, int out_size) {
    const float* feature     = (const float*)d_in[0];
    const float* feature_aug = (const float*)d_in[1];
    (void)in_sizes; (void)n_in; (void)out_size;

    static int configured = 0;
    if (!configured) {
        cudaFuncSetAttribute(pair_mma_kernel,
                             cudaFuncAttributeMaxDynamicSharedMemorySize, SMEM_DYN);
        configured = 1;
    }

    init_kernel<<<(BB * TT + 255) / 256, 256>>>();

    dim3 cgrid((NELEM / 4 + 255) / 256, 2);
    convert_kernel<<<cgrid, 256>>>(feature, feature_aug);

    dim3 grid(2, BB * BB * VV);  // (mtile) x 2048 pairs
    pair_mma_kernel<<<grid, 256, SMEM_DYN>>>();

    finalize_kernel<<<1, 1024>>>((float*)d_out);
}